// round 13
// baseline (speedup 1.0000x reference)
#include <cuda_runtime.h>
#include <cstdint>

#define NN 4096
#define FF 16
#define CM 512                   // X rows staged per chunk
#define NCHUNK (NN / CM)         // 8
#define XS_STRIDE (CM + 4)       // float stride per feature row in smem (pad)
#define THREADS 256
#define WARPS_PER_BLOCK 8
#define R 2                      // output rows per warp
#define ROWS_PER_BLOCK (WARPS_PER_BLOCK * R)   // 16
#define ROW1 (NN / 4)            // float4 offset between row n0 and n0+1
#define PFD 64                   // prefetch distance: 2 iterations = 64 float4s

#define PF(p) asm volatile("prefetch.global.L2 [%0];" :: "l"((const void*)(p)))

// X transposed: XT[f][m], 16 x 4096 (written by pre-kernel)
__device__ __align__(16) float g_XT[FF * NN];

// ---- pre-kernel: XT[f][m] = X[m][f] --------------------------------------
__global__ void __launch_bounds__(256)
transpose_x_kernel(const float* __restrict__ X)
{
    const int m = blockIdx.x * 256 + threadIdx.x;   // 4096 threads total
    const float4* xr = (const float4*)(X + (size_t)m * FF);
    float4 a = xr[0], b = xr[1], c = xr[2], d = xr[3];
    g_XT[ 0 * NN + m] = a.x;  g_XT[ 1 * NN + m] = a.y;
    g_XT[ 2 * NN + m] = a.z;  g_XT[ 3 * NN + m] = a.w;
    g_XT[ 4 * NN + m] = b.x;  g_XT[ 5 * NN + m] = b.y;
    g_XT[ 6 * NN + m] = b.z;  g_XT[ 7 * NN + m] = b.w;
    g_XT[ 8 * NN + m] = c.x;  g_XT[ 9 * NN + m] = c.y;
    g_XT[10 * NN + m] = c.z;  g_XT[11 * NN + m] = c.w;
    g_XT[12 * NN + m] = d.x;  g_XT[13 * NN + m] = d.y;
    g_XT[14 * NN + m] = d.z;  g_XT[15 * NN + m] = d.w;
}

// ---- main kernel ---------------------------------------------------------
__global__ void __launch_bounds__(THREADS, 2)
diffusion_conv_kernel(const float* __restrict__ X,
                      const float* __restrict__ theta,
                      const float* __restrict__ Wp,
                      const float* __restrict__ WTp,
                      float* __restrict__ out)
{
    // double-buffered transposed X chunks: Xs[buf][f*XS_STRIDE + m_local]
    __shared__ __align__(16) float Xs[2][FF * XS_STRIDE];

    const int tid  = threadIdx.x;
    const int warp = tid >> 5;
    const int lane = tid & 31;

    const int n0 = blockIdx.x * ROWS_PER_BLOCK + warp * R;   // first of 2 rows
    const size_t NN2 = (size_t)NN * NN;

    const float ta0 = theta[0], tb0 = theta[1];
    const float ta1 = theta[2], tb1 = theta[3];
    const float ta2 = theta[4], tb2 = theta[5];

    // 6 base pointers (k-planes); row n0+1 addressed via +ROW1 immediate.
    const float4* __restrict__ w0 = (const float4*)(Wp  + 0 * NN2 + (size_t)n0 * NN);
    const float4* __restrict__ w1 = (const float4*)(Wp  + 1 * NN2 + (size_t)n0 * NN);
    const float4* __restrict__ w2 = (const float4*)(Wp  + 2 * NN2 + (size_t)n0 * NN);
    const float4* __restrict__ v0 = (const float4*)(WTp + 0 * NN2 + (size_t)n0 * NN);
    const float4* __restrict__ v1 = (const float4*)(WTp + 1 * NN2 + (size_t)n0 * NN);
    const float4* __restrict__ v2 = (const float4*)(WTp + 2 * NN2 + (size_t)n0 * NN);

    float acc0[FF], acc1[FF];
#pragma unroll
    for (int f = 0; f < FF; f++) { acc0[f] = 0.0f; acc1[f] = 0.0f; }

    // issue cp.async staging of chunk c0 into buffer buf (reg-free, 8/thread)
    // each f-row piece: CM floats from g_XT[f*NN + c0] -> Xs[buf][f*XS_STRIDE]
#define STAGE_ASYNC(c0_, buf_)                                                \
    {                                                                         \
        _Pragma("unroll")                                                     \
        for (int k = 0; k < (FF * CM) / (4 * THREADS); k++) {                 \
            const int linear = k * THREADS + tid;   /* 16B-chunk index */     \
            const int f_   = linear >> 7;           /* CM/4 = 128 per row */  \
            const int mseg = linear & 127;                                    \
            const float* src = g_XT + f_ * NN + (c0_) + mseg * 4;             \
            unsigned int dst;                                                 \
            {                                                                 \
                const float* dp = &Xs[buf_][f_ * XS_STRIDE + mseg * 4];       \
                asm("{ .reg .u64 t; cvta.to.shared.u64 t, %1;"                \
                    " cvt.u32.u64 %0, t; }" : "=r"(dst) : "l"(dp));           \
            }                                                                 \
            asm volatile("cp.async.cg.shared.global [%0], [%1], 16;"          \
                         :: "r"(dst), "l"(src));                              \
        }                                                                     \
        asm volatile("cp.async.commit_group;");                               \
    }

    // prologue: stage chunk 0 into buffer 0 and wait
    STAGE_ASYNC(0, 0)
    asm volatile("cp.async.wait_group 0;");
    __syncthreads();

#pragma unroll 1
    for (int ch = 0; ch < NCHUNK; ch++) {
        const int cur = ch & 1;
        const int c0  = ch * CM;

        // fire-and-forget staging of next chunk (no regs, no issue stall;
        // W loads below are not blocked)
        if (ch + 1 < NCHUNK) {
            STAGE_ASYNC(c0 + CM, cur ^ 1)
        }

        // compute chunk ch from Xs[cur]; unroll 2 lets ptxas pipeline LDGs
#pragma unroll 2
        for (int it = 0; it < CM / 128; it++) {
            const int moff = it * 128 + 4 * lane;     // chunk-local m
            const int gidx = (c0 + moff) >> 2;        // float4 index in row

            // 12 LDG.128, streaming (use-once -> evict-first)
            float4 a00 = __ldcs(w0 + gidx);
            float4 a01 = __ldcs(w1 + gidx);
            float4 a02 = __ldcs(w2 + gidx);
            float4 b00 = __ldcs(v0 + gidx);
            float4 b01 = __ldcs(v1 + gidx);
            float4 b02 = __ldcs(v2 + gidx);
            float4 a10 = __ldcs(w0 + gidx + ROW1);
            float4 a11 = __ldcs(w1 + gidx + ROW1);
            float4 a12 = __ldcs(w2 + gidx + ROW1);
            float4 b10 = __ldcs(v0 + gidx + ROW1);
            float4 b11 = __ldcs(v1 + gidx + ROW1);
            float4 b12 = __ldcs(v2 + gidx + ROW1);

            // L2 prefetch 2 iterations ahead (1 lane per 128-B line)
            if ((lane & 7) == 0) {
                const int pg = gidx + PFD;
                PF(w0 + pg);        PF(w1 + pg);        PF(w2 + pg);
                PF(v0 + pg);        PF(v1 + pg);        PF(v2 + pg);
                PF(w0 + pg + ROW1); PF(w1 + pg + ROW1); PF(w2 + pg + ROW1);
                PF(v0 + pg + ROW1); PF(v1 + pg + ROW1); PF(v2 + pg + ROW1);
            }

            float4 M0, M1;
            M0.x = ta0 * a00.x + ta1 * a01.x + ta2 * a02.x
                 + tb0 * b00.x + tb1 * b01.x + tb2 * b02.x;
            M0.y = ta0 * a00.y + ta1 * a01.y + ta2 * a02.y
                 + tb0 * b00.y + tb1 * b01.y + tb2 * b02.y;
            M0.z = ta0 * a00.z + ta1 * a01.z + ta2 * a02.z
                 + tb0 * b00.z + tb1 * b01.z + tb2 * b02.z;
            M0.w = ta0 * a00.w + ta1 * a01.w + ta2 * a02.w
                 + tb0 * b00.w + tb1 * b01.w + tb2 * b02.w;
            M1.x = ta0 * a10.x + ta1 * a11.x + ta2 * a12.x
                 + tb0 * b10.x + tb1 * b11.x + tb2 * b12.x;
            M1.y = ta0 * a10.y + ta1 * a11.y + ta2 * a12.y
                 + tb0 * b10.y + tb1 * b11.y + tb2 * b12.y;
            M1.z = ta0 * a10.z + ta1 * a11.z + ta2 * a12.z
                 + tb0 * b10.z + tb1 * b11.z + tb2 * b12.z;
            M1.w = ta0 * a10.w + ta1 * a11.w + ta2 * a12.w
                 + tb0 * b10.w + tb1 * b11.w + tb2 * b12.w;

            const float* xb = &Xs[cur][0];
#pragma unroll
            for (int f = 0; f < FF; f++) {
                float4 xs = *(const float4*)&xb[f * XS_STRIDE + moff];
                acc0[f] += M0.x * xs.x + M0.y * xs.y
                         + M0.z * xs.z + M0.w * xs.w;
                acc1[f] += M1.x * xs.x + M1.y * xs.y
                         + M1.z * xs.z + M1.w * xs.w;
            }
        }

        // next chunk's staging has had 4 compute iterations to land
        asm volatile("cp.async.wait_group 0;");
        __syncthreads();
    }

    // butterfly-reduce each feature across the warp
#pragma unroll
    for (int f = 0; f < FF; f++) {
#pragma unroll
        for (int d = 16; d >= 1; d >>= 1) {
            acc0[f] += __shfl_xor_sync(0xFFFFFFFFu, acc0[f], d);
            acc1[f] += __shfl_xor_sync(0xFFFFFFFFu, acc1[f], d);
        }
    }

    if (lane == 0) {
        const float* x0 = X + (size_t)n0 * FF;
        float* o0 = out + (size_t)n0 * FF;
#pragma unroll
        for (int f = 0; f < FF; f++) {
            o0[f]      = x0[f]      + acc0[f];
            o0[FF + f] = x0[FF + f] + acc1[f];
        }
    }
}

extern "C" void kernel_launch(void* const* d_in, const int* in_sizes, int n_in,
                              void* d_out, int out_size)
{
    const float* X     = (const float*)d_in[0];   // [4096, 16]
    const float* theta = (const float*)d_in[1];   // [3, 2]
    const float* Wp    = (const float*)d_in[2];   // [3, 4096, 4096]
    const float* WTp   = (const float*)d_in[3];   // [3, 4096, 4096]
    float* out = (float*)d_out;                   // [4096, 16]

    transpose_x_kernel<<<NN / 256, 256>>>(X);     // XT[f][m] once (~2 us)

    dim3 grid(NN / ROWS_PER_BLOCK);               // 256 blocks
    dim3 block(THREADS);
    diffusion_conv_kernel<<<grid, block>>>(X, theta, Wp, WTp, out);
}

// round 14
// speedup vs baseline: 1.0392x; 1.0392x over previous
#include <cuda_runtime.h>

#define NN 4096
#define FF 16
#define CM 512                   // X rows staged per chunk
#define XS_STRIDE (CM + 4)       // float stride per feature row in smem (pad)
#define THREADS 256
#define WARPS_PER_BLOCK 8
#define NBLOCKS 296              // 2 x 148 SMs -> uniform 2 blocks/SM
#define NWARPS (NBLOCKS * WARPS_PER_BLOCK)     // 2368 warps over 4096 rows
#define ROW1 (NN / 4)            // float4 offset between adjacent rows
#define PFD 64                   // prefetch distance: 2 iterations = 64 float4s

#define PF(p) asm volatile("prefetch.global.L2 [%0];" :: "l"((const void*)(p)))

__global__ void __launch_bounds__(THREADS, 2)
diffusion_conv_kernel(const float* __restrict__ X,
                      const float* __restrict__ theta,
                      const float* __restrict__ Wp,
                      const float* __restrict__ WTp,
                      float* __restrict__ out)
{
    // X chunk, transposed: Xs[f][m_local], padded rows -> conflict-free LDS.128
    __shared__ __align__(16) float Xs[FF * XS_STRIDE];

    const int tid  = threadIdx.x;
    const int warp = tid >> 5;
    const int lane = tid & 31;

    // balanced row partition: warp gw owns rows [64*gw/37, 64*(gw+1)/37)
    const int gw   = blockIdx.x * WARPS_PER_BLOCK + warp;   // 0..2367
    const int rlo  = (64 * gw) / 37;
    const int rhi  = (64 * (gw + 1)) / 37;                  // rlo+1 or rlo+2
    const int n0   = rlo;
    const int dual = (rhi - rlo) == 2;       // 2 distinct rows?
    const int rof  = dual ? ROW1 : 0;        // float4 offset of 2nd row (0 = alias)

    const size_t NN2 = (size_t)NN * NN;

    const float ta0 = theta[0], tb0 = theta[1];
    const float ta1 = theta[2], tb1 = theta[3];
    const float ta2 = theta[4], tb2 = theta[5];

    // 6 base pointers (k-planes); 2nd row addressed via +rof (uniform reg)
    const float4* __restrict__ w0 = (const float4*)(Wp  + 0 * NN2 + (size_t)n0 * NN);
    const float4* __restrict__ w1 = (const float4*)(Wp  + 1 * NN2 + (size_t)n0 * NN);
    const float4* __restrict__ w2 = (const float4*)(Wp  + 2 * NN2 + (size_t)n0 * NN);
    const float4* __restrict__ v0 = (const float4*)(WTp + 0 * NN2 + (size_t)n0 * NN);
    const float4* __restrict__ v1 = (const float4*)(WTp + 1 * NN2 + (size_t)n0 * NN);
    const float4* __restrict__ v2 = (const float4*)(WTp + 2 * NN2 + (size_t)n0 * NN);

    float acc0[FF], acc1[FF];
#pragma unroll
    for (int f = 0; f < FF; f++) { acc0[f] = 0.0f; acc1[f] = 0.0f; }

    for (int c0 = 0; c0 < NN; c0 += CM) {
        __syncthreads();   // previous chunk fully consumed

        // stage X[c0 : c0+CM][:] transposed into Xs[f][m_local]
        for (int i = tid; i < CM; i += THREADS) {
            const float4* xr = (const float4*)(X + (size_t)(c0 + i) * FF);
            float4 a = xr[0], b = xr[1], c = xr[2], d = xr[3];
            Xs[ 0 * XS_STRIDE + i] = a.x;  Xs[ 1 * XS_STRIDE + i] = a.y;
            Xs[ 2 * XS_STRIDE + i] = a.z;  Xs[ 3 * XS_STRIDE + i] = a.w;
            Xs[ 4 * XS_STRIDE + i] = b.x;  Xs[ 5 * XS_STRIDE + i] = b.y;
            Xs[ 6 * XS_STRIDE + i] = b.z;  Xs[ 7 * XS_STRIDE + i] = b.w;
            Xs[ 8 * XS_STRIDE + i] = c.x;  Xs[ 9 * XS_STRIDE + i] = c.y;
            Xs[10 * XS_STRIDE + i] = c.z;  Xs[11 * XS_STRIDE + i] = c.w;
            Xs[12 * XS_STRIDE + i] = d.x;  Xs[13 * XS_STRIDE + i] = d.y;
            Xs[14 * XS_STRIDE + i] = d.z;  Xs[15 * XS_STRIDE + i] = d.w;
        }
        __syncthreads();

        // warp sweeps the chunk: lane owns 4 consecutive m, warp covers 128 m
        // for both rows per step. unroll 2 lets ptxas software-pipeline LDGs.
#pragma unroll 2
        for (int it = 0; it < CM / 128; it++) {
            const int moff = it * 128 + 4 * lane;     // chunk-local m
            const int gidx = (c0 + moff) >> 2;        // float4 index in row

            // 12 LDG.128, streaming (use-once -> evict-first); for single-row
            // warps the +rof loads alias row 0 (cache hits, no extra DRAM)
            float4 a00 = __ldcs(w0 + gidx);
            float4 a01 = __ldcs(w1 + gidx);
            float4 a02 = __ldcs(w2 + gidx);
            float4 b00 = __ldcs(v0 + gidx);
            float4 b01 = __ldcs(v1 + gidx);
            float4 b02 = __ldcs(v2 + gidx);
            float4 a10 = __ldcs(w0 + gidx + rof);
            float4 a11 = __ldcs(w1 + gidx + rof);
            float4 a12 = __ldcs(w2 + gidx + rof);
            float4 b10 = __ldcs(v0 + gidx + rof);
            float4 b11 = __ldcs(v1 + gidx + rof);
            float4 b12 = __ldcs(v2 + gidx + rof);

            // L2 prefetch 2 iterations ahead (1 lane per 128-B line)
            if ((lane & 7) == 0) {
                const int pg = gidx + PFD;
                PF(w0 + pg);       PF(w1 + pg);       PF(w2 + pg);
                PF(v0 + pg);       PF(v1 + pg);       PF(v2 + pg);
                PF(w0 + pg + rof); PF(w1 + pg + rof); PF(w2 + pg + rof);
                PF(v0 + pg + rof); PF(v1 + pg + rof); PF(v2 + pg + rof);
            }

            float4 M0, M1;
            M0.x = ta0 * a00.x + ta1 * a01.x + ta2 * a02.x
                 + tb0 * b00.x + tb1 * b01.x + tb2 * b02.x;
            M0.y = ta0 * a00.y + ta1 * a01.y + ta2 * a02.y
                 + tb0 * b00.y + tb1 * b01.y + tb2 * b02.y;
            M0.z = ta0 * a00.z + ta1 * a01.z + ta2 * a02.z
                 + tb0 * b00.z + tb1 * b01.z + tb2 * b02.z;
            M0.w = ta0 * a00.w + ta1 * a01.w + ta2 * a02.w
                 + tb0 * b00.w + tb1 * b01.w + tb2 * b02.w;
            M1.x = ta0 * a10.x + ta1 * a11.x + ta2 * a12.x
                 + tb0 * b10.x + tb1 * b11.x + tb2 * b12.x;
            M1.y = ta0 * a10.y + ta1 * a11.y + ta2 * a12.y
                 + tb0 * b10.y + tb1 * b11.y + tb2 * b12.y;
            M1.z = ta0 * a10.z + ta1 * a11.z + ta2 * a12.z
                 + tb0 * b10.z + tb1 * b11.z + tb2 * b12.z;
            M1.w = ta0 * a10.w + ta1 * a11.w + ta2 * a12.w
                 + tb0 * b10.w + tb1 * b11.w + tb2 * b12.w;

#pragma unroll
            for (int f = 0; f < FF; f++) {
                float4 xs = *(const float4*)&Xs[f * XS_STRIDE + moff];
                acc0[f] += M0.x * xs.x + M0.y * xs.y
                         + M0.z * xs.z + M0.w * xs.w;
                acc1[f] += M1.x * xs.x + M1.y * xs.y
                         + M1.z * xs.z + M1.w * xs.w;
            }
        }
    }

    // butterfly-reduce each feature across the warp
#pragma unroll
    for (int f = 0; f < FF; f++) {
#pragma unroll
        for (int d = 16; d >= 1; d >>= 1) {
            acc0[f] += __shfl_xor_sync(0xFFFFFFFFu, acc0[f], d);
            acc1[f] += __shfl_xor_sync(0xFFFFFFFFu, acc1[f], d);
        }
    }

    if (lane == 0) {
        const float* x0 = X + (size_t)n0 * FF;
        float* o0 = out + (size_t)n0 * FF;
#pragma unroll
        for (int f = 0; f < FF; f++)
            o0[f] = x0[f] + acc0[f];
        if (dual) {
#pragma unroll
            for (int f = 0; f < FF; f++)
                o0[FF + f] = x0[FF + f] + acc1[f];
        }
    }
}

extern "C" void kernel_launch(void* const* d_in, const int* in_sizes, int n_in,
                              void* d_out, int out_size)
{
    const float* X     = (const float*)d_in[0];   // [4096, 16]
    const float* theta = (const float*)d_in[1];   // [3, 2]
    const float* Wp    = (const float*)d_in[2];   // [3, 4096, 4096]
    const float* WTp   = (const float*)d_in[3];   // [3, 4096, 4096]
    float* out = (float*)d_out;                   // [4096, 16]

    dim3 grid(NBLOCKS);                           // 296 = 2 per SM, uniform
    dim3 block(THREADS);
    diffusion_conv_kernel<<<grid, block>>>(X, theta, Wp, WTp, out);
}

// round 15
// speedup vs baseline: 1.0435x; 1.0041x over previous
#include <cuda_runtime.h>

#define NN 4096
#define FF 16
#define CM 512                   // X rows staged per chunk
#define XS_STRIDE (CM + 4)       // float stride per feature row in smem (pad)
#define THREADS 256
#define WARPS_PER_BLOCK 8
#define R 2                      // output rows per warp
#define ROWS_PER_BLOCK (WARPS_PER_BLOCK * R)   // 16
#define ROW1 (NN / 4)            // float4 offset between row n0 and n0+1
#define PFD 96                   // prefetch distance: 3 iterations ahead

#define PF(p) asm volatile("prefetch.global.L2 [%0];" :: "l"((const void*)(p)))

__global__ void __launch_bounds__(THREADS, 2)
diffusion_conv_kernel(const float* __restrict__ X,
                      const float* __restrict__ theta,
                      const float* __restrict__ Wp,
                      const float* __restrict__ WTp,
                      float* __restrict__ out)
{
    // X chunk, transposed: Xs[f][m_local], padded rows -> conflict-free LDS.128
    __shared__ __align__(16) float Xs[FF * XS_STRIDE];

    const int tid  = threadIdx.x;
    const int warp = tid >> 5;
    const int lane = tid & 31;

    const int n0 = blockIdx.x * ROWS_PER_BLOCK + warp * R;   // first of 2 rows
    const size_t NN2 = (size_t)NN * NN;

    const float ta0 = theta[0], tb0 = theta[1];
    const float ta1 = theta[2], tb1 = theta[3];
    const float ta2 = theta[4], tb2 = theta[5];

    // 6 base pointers (k-planes); row n0+1 addressed via +ROW1 immediate.
    const float4* __restrict__ w0 = (const float4*)(Wp  + 0 * NN2 + (size_t)n0 * NN);
    const float4* __restrict__ w1 = (const float4*)(Wp  + 1 * NN2 + (size_t)n0 * NN);
    const float4* __restrict__ w2 = (const float4*)(Wp  + 2 * NN2 + (size_t)n0 * NN);
    const float4* __restrict__ v0 = (const float4*)(WTp + 0 * NN2 + (size_t)n0 * NN);
    const float4* __restrict__ v1 = (const float4*)(WTp + 1 * NN2 + (size_t)n0 * NN);
    const float4* __restrict__ v2 = (const float4*)(WTp + 2 * NN2 + (size_t)n0 * NN);

    float acc0[FF], acc1[FF];
#pragma unroll
    for (int f = 0; f < FF; f++) { acc0[f] = 0.0f; acc1[f] = 0.0f; }

    for (int c0 = 0; c0 < NN; c0 += CM) {
        __syncthreads();   // previous chunk fully consumed

        // stage X[c0 : c0+CM][:] transposed into Xs[f][m_local]
        for (int i = tid; i < CM; i += THREADS) {
            const float4* xr = (const float4*)(X + (size_t)(c0 + i) * FF);
            float4 a = xr[0], b = xr[1], c = xr[2], d = xr[3];
            Xs[ 0 * XS_STRIDE + i] = a.x;  Xs[ 1 * XS_STRIDE + i] = a.y;
            Xs[ 2 * XS_STRIDE + i] = a.z;  Xs[ 3 * XS_STRIDE + i] = a.w;
            Xs[ 4 * XS_STRIDE + i] = b.x;  Xs[ 5 * XS_STRIDE + i] = b.y;
            Xs[ 6 * XS_STRIDE + i] = b.z;  Xs[ 7 * XS_STRIDE + i] = b.w;
            Xs[ 8 * XS_STRIDE + i] = c.x;  Xs[ 9 * XS_STRIDE + i] = c.y;
            Xs[10 * XS_STRIDE + i] = c.z;  Xs[11 * XS_STRIDE + i] = c.w;
            Xs[12 * XS_STRIDE + i] = d.x;  Xs[13 * XS_STRIDE + i] = d.y;
            Xs[14 * XS_STRIDE + i] = d.z;  Xs[15 * XS_STRIDE + i] = d.w;
        }
        __syncthreads();

        // warp sweeps the chunk: lane owns 4 consecutive m, warp covers 128 m
        // for BOTH rows per step. FULL unroll (4 iterations) gives ptxas the
        // whole sweep to software-pipeline LDG batches under the reg cap.
#pragma unroll
        for (int it = 0; it < CM / 128; it++) {
            const int moff = it * 128 + 4 * lane;     // chunk-local m
            const int gidx = (c0 + moff) >> 2;        // float4 index in row

            // 12 LDG.128, streaming (use-once -> evict-first)
            float4 a00 = __ldcs(w0 + gidx);
            float4 a01 = __ldcs(w1 + gidx);
            float4 a02 = __ldcs(w2 + gidx);
            float4 b00 = __ldcs(v0 + gidx);
            float4 b01 = __ldcs(v1 + gidx);
            float4 b02 = __ldcs(v2 + gidx);
            float4 a10 = __ldcs(w0 + gidx + ROW1);
            float4 a11 = __ldcs(w1 + gidx + ROW1);
            float4 a12 = __ldcs(w2 + gidx + ROW1);
            float4 b10 = __ldcs(v0 + gidx + ROW1);
            float4 b11 = __ldcs(v1 + gidx + ROW1);
            float4 b12 = __ldcs(v2 + gidx + ROW1);

            // L2 prefetch 3 iterations ahead (1 lane per 128-B line)
            if ((lane & 7) == 0) {
                const int pg = gidx + PFD;
                PF(w0 + pg);        PF(w1 + pg);        PF(w2 + pg);
                PF(v0 + pg);        PF(v1 + pg);        PF(v2 + pg);
                PF(w0 + pg + ROW1); PF(w1 + pg + ROW1); PF(w2 + pg + ROW1);
                PF(v0 + pg + ROW1); PF(v1 + pg + ROW1); PF(v2 + pg + ROW1);
            }

            float4 M0, M1;
            M0.x = ta0 * a00.x + ta1 * a01.x + ta2 * a02.x
                 + tb0 * b00.x + tb1 * b01.x + tb2 * b02.x;
            M0.y = ta0 * a00.y + ta1 * a01.y + ta2 * a02.y
                 + tb0 * b00.y + tb1 * b01.y + tb2 * b02.y;
            M0.z = ta0 * a00.z + ta1 * a01.z + ta2 * a02.z
                 + tb0 * b00.z + tb1 * b01.z + tb2 * b02.z;
            M0.w = ta0 * a00.w + ta1 * a01.w + ta2 * a02.w
                 + tb0 * b00.w + tb1 * b01.w + tb2 * b02.w;
            M1.x = ta0 * a10.x + ta1 * a11.x + ta2 * a12.x
                 + tb0 * b10.x + tb1 * b11.x + tb2 * b12.x;
            M1.y = ta0 * a10.y + ta1 * a11.y + ta2 * a12.y
                 + tb0 * b10.y + tb1 * b11.y + tb2 * b12.y;
            M1.z = ta0 * a10.z + ta1 * a11.z + ta2 * a12.z
                 + tb0 * b10.z + tb1 * b11.z + tb2 * b12.z;
            M1.w = ta0 * a10.w + ta1 * a11.w + ta2 * a12.w
                 + tb0 * b10.w + tb1 * b11.w + tb2 * b12.w;

#pragma unroll
            for (int f = 0; f < FF; f++) {
                float4 xs = *(const float4*)&Xs[f * XS_STRIDE + moff];
                acc0[f] += M0.x * xs.x + M0.y * xs.y
                         + M0.z * xs.z + M0.w * xs.w;
                acc1[f] += M1.x * xs.x + M1.y * xs.y
                         + M1.z * xs.z + M1.w * xs.w;
            }
        }
    }

    // butterfly-reduce each feature across the warp
#pragma unroll
    for (int f = 0; f < FF; f++) {
#pragma unroll
        for (int d = 16; d >= 1; d >>= 1) {
            acc0[f] += __shfl_xor_sync(0xFFFFFFFFu, acc0[f], d);
            acc1[f] += __shfl_xor_sync(0xFFFFFFFFu, acc1[f], d);
        }
    }

    if (lane == 0) {
        const float* x0 = X + (size_t)n0 * FF;
        float* o0 = out + (size_t)n0 * FF;
#pragma unroll
        for (int f = 0; f < FF; f++) {
            o0[f]      = x0[f]      + acc0[f];
            o0[FF + f] = x0[FF + f] + acc1[f];
        }
    }
}

extern "C" void kernel_launch(void* const* d_in, const int* in_sizes, int n_in,
                              void* d_out, int out_size)
{
    const float* X     = (const float*)d_in[0];   // [4096, 16]
    const float* theta = (const float*)d_in[1];   // [3, 2]
    const float* Wp    = (const float*)d_in[2];   // [3, 4096, 4096]
    const float* WTp   = (const float*)d_in[3];   // [3, 4096, 4096]
    float* out = (float*)d_out;                   // [4096, 16]

    dim3 grid(NN / ROWS_PER_BLOCK);               // 256 blocks
    dim3 block(THREADS);
    diffusion_conv_kernel<<<grid, block>>>(X, theta, Wp, WTp, out);
}